// round 1
// baseline (speedup 1.0000x reference)
#include <cuda_runtime.h>
#include <cstdint>

// Problem constants
constexpr int kB = 2, kS = 2048, kH = 512, kNH = 8, kDK = 64;
constexpr int kBH = kB * kNH;

// Scratch: projected q/k/v in [b,h,s,d] layout (device globals — no allocs)
__device__ float g_q[kBH * kS * kDK];
__device__ float g_k[kBH * kS * kDK];
__device__ float g_v[kBH * kS * kDK];

__device__ __forceinline__ unsigned f2tf(float x) {
    unsigned r;
    asm("cvt.rna.tf32.f32 %0, %1;" : "=r"(r) : "f"(x));
    return r;
}
__device__ __forceinline__ float tfval(float x) {  // round fp32 -> tf32 value
    return __uint_as_float(f2tf(x));
}

// D += A(16x8) * B(8x8), tf32 inputs, fp32 accum.
// A frags: a0:(g,t) a1:(g+8,t) a2:(g,t+4) a3:(g+8,t+4)
// B frags: b0:(k=t,n=g) b1:(k=t+4,n=g)
// C frags: c0:(g,2t) c1:(g,2t+1) c2:(g+8,2t) c3:(g+8,2t+1)
__device__ __forceinline__ void mma_tf32(float& d0, float& d1, float& d2, float& d3,
                                         unsigned a0, unsigned a1, unsigned a2, unsigned a3,
                                         unsigned b0, unsigned b1) {
    asm volatile(
        "mma.sync.aligned.m16n8k8.row.col.f32.tf32.tf32.f32 "
        "{%0,%1,%2,%3}, {%4,%5,%6,%7}, {%8,%9}, {%0,%1,%2,%3};\n"
        : "+f"(d0), "+f"(d1), "+f"(d2), "+f"(d3)
        : "r"(a0), "r"(a1), "r"(a2), "r"(a3), "r"(b0), "r"(b1));
}

// ============================================================================
// Projection: Y = X @ W^T + b, X [4096,512], W [512,512] (both K-contiguous).
// 3xTF32 split (hi*hi + hi*lo + lo*hi) for near-fp32 accuracy.
// Output scattered to [b,h,s,d] layout.
// ============================================================================
constexpr int PBM = 128, PBN = 64, PBK = 16, PST = 20;  // stride 20: conflict-free frags

__global__ __launch_bounds__(256, 1) void proj_kernel(
    const float* __restrict__ X, const float* __restrict__ W,
    const float* __restrict__ bias, int which)
{
    __shared__ float Xh[PBM * PST], Xl[PBM * PST];
    __shared__ float Wh[PBN * PST], Wl[PBN * PST];

    const int tid  = threadIdx.x;
    const int warp = tid >> 5, lane = tid & 31;
    const int g = lane >> 2, t = lane & 3;
    const int m0 = blockIdx.x * PBM;
    const int n0 = blockIdx.y * PBN;
    const int rw = warp * 16;

    float acc[8][4];
#pragma unroll
    for (int j = 0; j < 8; j++) { acc[j][0] = acc[j][1] = acc[j][2] = acc[j][3] = 0.f; }

    for (int k0 = 0; k0 < kH; k0 += PBK) {
        __syncthreads();
        // X tile 128x16: 512 float4, 2 per thread
#pragma unroll
        for (int i = 0; i < 2; i++) {
            int v = tid + i * 256;
            int r = v >> 2, c4 = v & 3;
            float4 x = *(const float4*)&X[(size_t)(m0 + r) * kH + k0 + c4 * 4];
            float* ph = &Xh[r * PST + c4 * 4];
            float* pl = &Xl[r * PST + c4 * 4];
            float h0 = tfval(x.x); ph[0] = h0; pl[0] = tfval(x.x - h0);
            float h1 = tfval(x.y); ph[1] = h1; pl[1] = tfval(x.y - h1);
            float h2 = tfval(x.z); ph[2] = h2; pl[2] = tfval(x.z - h2);
            float h3 = tfval(x.w); ph[3] = h3; pl[3] = tfval(x.w - h3);
        }
        // W tile 64x16: 256 float4, 1 per thread
        {
            int r = tid >> 2, c4 = tid & 3;
            float4 x = *(const float4*)&W[(size_t)(n0 + r) * kH + k0 + c4 * 4];
            float* ph = &Wh[r * PST + c4 * 4];
            float* pl = &Wl[r * PST + c4 * 4];
            float h0 = tfval(x.x); ph[0] = h0; pl[0] = tfval(x.x - h0);
            float h1 = tfval(x.y); ph[1] = h1; pl[1] = tfval(x.y - h1);
            float h2 = tfval(x.z); ph[2] = h2; pl[2] = tfval(x.z - h2);
            float h3 = tfval(x.w); ph[3] = h3; pl[3] = tfval(x.w - h3);
        }
        __syncthreads();

#pragma unroll
        for (int kk = 0; kk < 2; kk++) {
            const int ko = kk * 8;
            unsigned ah0 = __float_as_uint(Xh[(rw + g)     * PST + ko + t]);
            unsigned ah1 = __float_as_uint(Xh[(rw + g + 8) * PST + ko + t]);
            unsigned ah2 = __float_as_uint(Xh[(rw + g)     * PST + ko + t + 4]);
            unsigned ah3 = __float_as_uint(Xh[(rw + g + 8) * PST + ko + t + 4]);
            unsigned al0 = __float_as_uint(Xl[(rw + g)     * PST + ko + t]);
            unsigned al1 = __float_as_uint(Xl[(rw + g + 8) * PST + ko + t]);
            unsigned al2 = __float_as_uint(Xl[(rw + g)     * PST + ko + t + 4]);
            unsigned al3 = __float_as_uint(Xl[(rw + g + 8) * PST + ko + t + 4]);
#pragma unroll
            for (int j = 0; j < 8; j++) {
                unsigned bh0 = __float_as_uint(Wh[(8 * j + g) * PST + ko + t]);
                unsigned bh1 = __float_as_uint(Wh[(8 * j + g) * PST + ko + t + 4]);
                unsigned bl0 = __float_as_uint(Wl[(8 * j + g) * PST + ko + t]);
                unsigned bl1 = __float_as_uint(Wl[(8 * j + g) * PST + ko + t + 4]);
                mma_tf32(acc[j][0], acc[j][1], acc[j][2], acc[j][3], ah0, ah1, ah2, ah3, bh0, bh1);
                mma_tf32(acc[j][0], acc[j][1], acc[j][2], acc[j][3], ah0, ah1, ah2, ah3, bl0, bl1);
                mma_tf32(acc[j][0], acc[j][1], acc[j][2], acc[j][3], al0, al1, al2, al3, bh0, bh1);
            }
        }
    }

    float* dst = (which == 0) ? g_q : (which == 1) ? g_k : g_v;
    const int hh = n0 >> 6;           // == blockIdx.y (BN == DK)
    const int r0 = m0 + rw + g;
    const int bb = r0 >> 11;
    const int s0 = r0 & (kS - 1);
#pragma unroll
    for (int j = 0; j < 8; j++) {
        int d = 8 * j + 2 * t;
        float bi0 = bias[n0 + d], bi1 = bias[n0 + d + 1];
        size_t o0 = ((size_t)(bb * kNH + hh) * kS + s0) * kDK + d;
        *(float2*)&dst[o0]            = make_float2(acc[j][0] + bi0, acc[j][1] + bi1);
        *(float2*)&dst[o0 + 8 * kDK]  = make_float2(acc[j][2] + bi0, acc[j][3] + bi1);
    }
}

// ============================================================================
// Flash attention: Q tile 128 (register frags), K/V tiles 64 in smem (tf32),
// online softmax, P re-fragmented via per-warp smem (aliases dead Q tile).
// score = QK^T/8 + mask[b,k];  where bias[b,0,q,k]==0 -> -1e30; softmax; @V.
// ============================================================================
constexpr int QT = 128, KT = 64, AST = 72;  // AST=72: conflict-free frag access
constexpr int ATT_SMEM = (QT * AST + 2 * KT * AST + KT) * 4;

__global__ __launch_bounds__(256, 1) void attn_kernel(
    const float* __restrict__ bias, const int* __restrict__ mask,
    float* __restrict__ out)
{
    extern __shared__ float sm[];
    float* Qs = sm;                    // 128x72, reused as Ps after frag preload
    float* Ks = Qs + QT * AST;         // 64x72
    float* Vs = Ks + KT * AST;         // 64x72
    float* Mf = Vs + KT * AST;         // 64

    const int tid  = threadIdx.x;
    const int warp = tid >> 5, lane = tid & 31;
    const int g = lane >> 2, t = lane & 3;
    const int qt = blockIdx.x, bh = blockIdx.y;
    const int b = bh >> 3, h = bh & 7;
    const int rw = warp * 16;

    const float* qptr = g_q + (size_t)(bh * kS + qt * QT) * kDK;
    const float* kptr = g_k + (size_t)bh * kS * kDK;
    const float* vptr = g_v + (size_t)bh * kS * kDK;

    // Load Q tile, fold 1/sqrt(64), round to tf32
#pragma unroll
    for (int i = 0; i < 8; i++) {
        int v = tid + i * 256;                 // 0..2047
        int r = v >> 4, c4 = v & 15;
        float4 x = *(const float4*)&qptr[(size_t)r * kDK + c4 * 4];
        float* p = &Qs[r * AST + c4 * 4];
        p[0] = tfval(x.x * 0.125f); p[1] = tfval(x.y * 0.125f);
        p[2] = tfval(x.z * 0.125f); p[3] = tfval(x.w * 0.125f);
    }
    __syncthreads();

    // Preload Q A-fragments for all 8 k-steps (Qs dead afterwards -> alias Ps)
    unsigned qf[8][4];
#pragma unroll
    for (int kk = 0; kk < 8; kk++) {
        qf[kk][0] = __float_as_uint(Qs[(rw + g)     * AST + kk * 8 + t]);
        qf[kk][1] = __float_as_uint(Qs[(rw + g + 8) * AST + kk * 8 + t]);
        qf[kk][2] = __float_as_uint(Qs[(rw + g)     * AST + kk * 8 + t + 4]);
        qf[kk][3] = __float_as_uint(Qs[(rw + g + 8) * AST + kk * 8 + t + 4]);
    }
    float* Ps = Qs;

    float o[8][4];
#pragma unroll
    for (int j = 0; j < 8; j++) { o[j][0] = o[j][1] = o[j][2] = o[j][3] = 0.f; }
    float mrow0 = -3.0e38f, mrow1 = -3.0e38f, l0 = 0.f, l1 = 0.f;

    const float* brow0 = bias + ((size_t)b * kS + qt * QT + rw + g) * kS;
    const float* brow1 = brow0 + (size_t)8 * kS;
    const int*   mrow  = mask + b * kS;

    for (int kv0 = 0; kv0 < kS; kv0 += KT) {
        __syncthreads();   // protect Ks/Vs from overwrite while prior O-gemm reads
        // Load K and V tiles (64x64 each) as tf32
#pragma unroll
        for (int i = 0; i < 4; i++) {
            int v = tid + i * 256;             // 0..1023
            int r = v >> 4, c4 = v & 15;
            float4 x = *(const float4*)&kptr[(size_t)(kv0 + r) * kDK + c4 * 4];
            float* pk = &Ks[r * AST + c4 * 4];
            pk[0] = tfval(x.x); pk[1] = tfval(x.y); pk[2] = tfval(x.z); pk[3] = tfval(x.w);
            float4 y = *(const float4*)&vptr[(size_t)(kv0 + r) * kDK + c4 * 4];
            float* pv = &Vs[r * AST + c4 * 4];
            pv[0] = tfval(y.x); pv[1] = tfval(y.y); pv[2] = tfval(y.z); pv[3] = tfval(y.w);
        }
        if (tid < KT) Mf[tid] = (float)mrow[kv0 + tid];
        __syncthreads();

        // S = Q * K^T  (scaled Q already)
        float c[8][4];
#pragma unroll
        for (int j = 0; j < 8; j++) { c[j][0] = c[j][1] = c[j][2] = c[j][3] = 0.f; }
#pragma unroll
        for (int kk = 0; kk < 8; kk++) {
#pragma unroll
            for (int j = 0; j < 8; j++) {
                unsigned b0 = __float_as_uint(Ks[(8 * j + g) * AST + kk * 8 + t]);
                unsigned b1 = __float_as_uint(Ks[(8 * j + g) * AST + kk * 8 + t + 4]);
                mma_tf32(c[j][0], c[j][1], c[j][2], c[j][3],
                         qf[kk][0], qf[kk][1], qf[kk][2], qf[kk][3], b0, b1);
            }
        }

        // + mask[b,k]; bias==0 -> -1e30; tile row max
        float tm0 = -3.0e38f, tm1 = -3.0e38f;
#pragma unroll
        for (int j = 0; j < 8; j++) {
            int cc = 8 * j + 2 * t;
            float ma0 = Mf[cc], ma1 = Mf[cc + 1];
            float2 bv0 = *(const float2*)&brow0[kv0 + cc];
            float2 bv1 = *(const float2*)&brow1[kv0 + cc];
            c[j][0] = (bv0.x == 0.f) ? -1e30f : c[j][0] + ma0;
            c[j][1] = (bv0.y == 0.f) ? -1e30f : c[j][1] + ma1;
            c[j][2] = (bv1.x == 0.f) ? -1e30f : c[j][2] + ma0;
            c[j][3] = (bv1.y == 0.f) ? -1e30f : c[j][3] + ma1;
            tm0 = fmaxf(tm0, fmaxf(c[j][0], c[j][1]));
            tm1 = fmaxf(tm1, fmaxf(c[j][2], c[j][3]));
        }
        tm0 = fmaxf(tm0, __shfl_xor_sync(0xffffffffu, tm0, 1));
        tm0 = fmaxf(tm0, __shfl_xor_sync(0xffffffffu, tm0, 2));
        tm1 = fmaxf(tm1, __shfl_xor_sync(0xffffffffu, tm1, 1));
        tm1 = fmaxf(tm1, __shfl_xor_sync(0xffffffffu, tm1, 2));

        float mn0 = fmaxf(mrow0, tm0), mn1 = fmaxf(mrow1, tm1);
        float al0 = __expf(mrow0 - mn0), al1 = __expf(mrow1 - mn1);
        mrow0 = mn0; mrow1 = mn1;

        float s0 = 0.f, s1 = 0.f;
#pragma unroll
        for (int j = 0; j < 8; j++) {
            float p0 = __expf(c[j][0] - mn0), p1 = __expf(c[j][1] - mn0);
            float p2 = __expf(c[j][2] - mn1), p3 = __expf(c[j][3] - mn1);
            s0 += p0 + p1; s1 += p2 + p3;
            int cc = 8 * j + 2 * t;
            *(float2*)&Ps[(rw + g)     * AST + cc] = make_float2(tfval(p0), tfval(p1));
            *(float2*)&Ps[(rw + g + 8) * AST + cc] = make_float2(tfval(p2), tfval(p3));
            o[j][0] *= al0; o[j][1] *= al0; o[j][2] *= al1; o[j][3] *= al1;
        }
        s0 += __shfl_xor_sync(0xffffffffu, s0, 1);
        s0 += __shfl_xor_sync(0xffffffffu, s0, 2);
        s1 += __shfl_xor_sync(0xffffffffu, s1, 1);
        s1 += __shfl_xor_sync(0xffffffffu, s1, 2);
        l0 = l0 * al0 + s0;
        l1 = l1 * al1 + s1;

        __syncwarp();  // Ps stores visible to the whole warp (per-warp rows only)

        // O += P * V
#pragma unroll
        for (int kk = 0; kk < 8; kk++) {
            unsigned a0 = __float_as_uint(Ps[(rw + g)     * AST + kk * 8 + t]);
            unsigned a1 = __float_as_uint(Ps[(rw + g + 8) * AST + kk * 8 + t]);
            unsigned a2 = __float_as_uint(Ps[(rw + g)     * AST + kk * 8 + t + 4]);
            unsigned a3 = __float_as_uint(Ps[(rw + g + 8) * AST + kk * 8 + t + 4]);
#pragma unroll
            for (int j = 0; j < 8; j++) {
                unsigned b0 = __float_as_uint(Vs[(kk * 8 + t)     * AST + 8 * j + g]);
                unsigned b1 = __float_as_uint(Vs[(kk * 8 + t + 4) * AST + 8 * j + g]);
                mma_tf32(o[j][0], o[j][1], o[j][2], o[j][3], a0, a1, a2, a3, b0, b1);
            }
        }
    }

    const float inv0 = 1.f / l0, inv1 = 1.f / l1;
    const int q0 = qt * QT + rw + g;
    float* orow0 = out + ((size_t)b * kS + q0) * kH + h * kDK;
    float* orow1 = orow0 + (size_t)8 * kH;
#pragma unroll
    for (int j = 0; j < 8; j++) {
        int cc = 8 * j + 2 * t;
        *(float2*)&orow0[cc] = make_float2(o[j][0] * inv0, o[j][1] * inv0);
        *(float2*)&orow1[cc] = make_float2(o[j][2] * inv1, o[j][3] * inv1);
    }
}

// ============================================================================
extern "C" void kernel_launch(void* const* d_in, const int* in_sizes, int n_in,
                              void* d_out, int out_size) {
    const float* query = (const float*)d_in[0];
    const float* key   = (const float*)d_in[1];
    const float* value = (const float*)d_in[2];
    const float* bias  = (const float*)d_in[3];
    const int*   mask  = (const int*)d_in[4];
    const float* Wq    = (const float*)d_in[5];
    const float* bq    = (const float*)d_in[6];
    const float* Wk    = (const float*)d_in[7];
    const float* bk    = (const float*)d_in[8];
    const float* Wv    = (const float*)d_in[9];
    const float* bv    = (const float*)d_in[10];
    float* out = (float*)d_out;

    cudaFuncSetAttribute(attn_kernel, cudaFuncAttributeMaxDynamicSharedMemorySize, ATT_SMEM);

    dim3 pgrid(kB * kS / PBM, kH / PBN);
    proj_kernel<<<pgrid, 256>>>(query, Wq, bq, 0);
    proj_kernel<<<pgrid, 256>>>(key,   Wk, bk, 1);
    proj_kernel<<<pgrid, 256>>>(value, Wv, bv, 2);

    attn_kernel<<<dim3(kS / QT, kBH), 256, ATT_SMEM>>>(bias, mask, out);
}